// round 8
// baseline (speedup 1.0000x reference)
#include <cuda_runtime.h>

#define BN  8
#define CIN 64
#define HH  56
#define WW  56
#define HW  (HH*WW)
#define OCM 128

// Scratch offset maps (dy/dx/mask-logit conv outputs)
__device__ float g_om3[BN * 27 * HW];
__device__ float g_om5[BN * 75 * HW];

typedef unsigned long long u64;

__device__ __forceinline__ u64 pack2(float lo, float hi) {
    u64 r; asm("mov.b64 %0, {%1, %2};" : "=l"(r) : "f"(lo), "f"(hi)); return r;
}
__device__ __forceinline__ void ffma2(u64 &d, u64 a, u64 b) {
    asm("fma.rn.f32x2 %0, %1, %2, %0;" : "+l"(d) : "l"(a), "l"(b));
}
__device__ __forceinline__ float2 unpack2(u64 v) {
    float2 f; asm("mov.b64 {%0, %1}, %2;" : "=f"(f.x), "=f"(f.y) : "l"(v)); return f;
}

// ---------------------------------------------------------------------------
// Offset conv. One block per (b, row-pair). 256 threads = 8 warps.
// Weights packed ws4[pair][t2h] = (tA.o0, tA.o1, tB.o0, tB.o1) -> aligned
// LDS.128 broadcast feeds 2 taps. Lane owns 4 pixels.
// ---------------------------------------------------------------------------
template<int K>
__global__ void __launch_bounds__(256, 2) offset_conv_kernel(
    const float* __restrict__ x, const float* __restrict__ ow,
    const float* __restrict__ ob)
{
    constexpr int K2  = K * K;
    constexpr int K2h = (K2 + 1) / 2;                 // tap pairs (padded)
    constexpr int P   = K / 2;
    constexpr int OCF = 3 * K2;
    constexpr int NPT = (((OCF + 1) / 2) + 7) & ~7;   // och pairs, padded to 8
    constexpr int NP  = NPT / 8;
    constexpr int R   = K + 1;

    float* __restrict__ om = (K == 3) ? g_om3 : g_om5;

    __shared__ __align__(16) float4 ws4[2][NPT * K2h];
    __shared__ float xs[2][R][72];

    const int b    = blockIdx.x / (HH / 2);
    const int yp   = blockIdx.x % (HH / 2);
    const int y0   = yp * 2;
    const int tid  = threadIdx.x;
    const int lane = tid & 31;
    const int g    = tid >> 5;

    u64 acc[NP * 4] = {};

    auto fill = [&](int c, int buf) {
        for (int i = tid; i < NPT * K2h; i += 256) {
            int p = i / K2h, t2h = i - p * K2h;
            int ta = 2 * t2h, tb = ta + 1;
            int o0 = 2 * p, o1 = o0 + 1;
            float4 v = make_float4(0.f, 0.f, 0.f, 0.f);
            if (o0 < OCF) {
                v.x = ow[(o0 * CIN + c) * K2 + ta];
                if (tb < K2) v.z = ow[(o0 * CIN + c) * K2 + tb];
            }
            if (o1 < OCF) {
                v.y = ow[(o1 * CIN + c) * K2 + ta];
                if (tb < K2) v.w = ow[(o1 * CIN + c) * K2 + tb];
            }
            ws4[buf][i] = v;
        }
        for (int i = tid; i < R * 72; i += 256) {
            int r = i / 72, col = i - r * 72;
            int yy = y0 - P + r, xx = col - P;
            float v = 0.f;
            if (yy >= 0 && yy < HH && xx >= 0 && xx < WW)
                v = x[((b * CIN + c) * HH + yy) * WW + xx];
            xs[buf][r][col] = v;
        }
    };

    fill(0, 0);
    __syncthreads();

    for (int c = 0; c < CIN; c++) {
        int cur = c & 1;
        if (c + 1 < CIN) fill(c + 1, cur ^ 1);

        const ulonglong2* wrow = (const ulonglong2*)(ws4[cur] + g * NP * K2h);
#pragma unroll
        for (int t2h = 0; t2h < K2h; t2h++) {
            int ta = 2 * t2h;
            int tb = (ta + 1 < K2) ? ta + 1 : ta;     // pad tap: weight is 0
            int ra = ta / K, da = ta % K;
            int rb = tb / K, db = tb % K;
            u64 A0 = pack2(xs[cur][ra][lane + da],      xs[cur][ra][lane + da]);
            u64 A1 = pack2(xs[cur][ra][lane + 32 + da], xs[cur][ra][lane + 32 + da]);
            u64 A2 = pack2(xs[cur][ra + 1][lane + da],      xs[cur][ra + 1][lane + da]);
            u64 A3 = pack2(xs[cur][ra + 1][lane + 32 + da], xs[cur][ra + 1][lane + 32 + da]);
            u64 B0 = pack2(xs[cur][rb][lane + db],      xs[cur][rb][lane + db]);
            u64 B1 = pack2(xs[cur][rb][lane + 32 + db], xs[cur][rb][lane + 32 + db]);
            u64 B2 = pack2(xs[cur][rb + 1][lane + db],      xs[cur][rb + 1][lane + db]);
            u64 B3 = pack2(xs[cur][rb + 1][lane + 32 + db], xs[cur][rb + 1][lane + 32 + db]);
#pragma unroll
            for (int j = 0; j < NP; j++) {
                ulonglong2 wv = wrow[j * K2h + t2h];   // LDS.128 broadcast
                ffma2(acc[4 * j],     A0, wv.x);
                ffma2(acc[4 * j + 1], A1, wv.x);
                ffma2(acc[4 * j + 2], A2, wv.x);
                ffma2(acc[4 * j + 3], A3, wv.x);
                ffma2(acc[4 * j],     B0, wv.y);
                ffma2(acc[4 * j + 1], B1, wv.y);
                ffma2(acc[4 * j + 2], B2, wv.y);
                ffma2(acc[4 * j + 3], B3, wv.y);
            }
        }
        __syncthreads();
    }

#pragma unroll
    for (int j = 0; j < NP; j++) {
        int o0 = (g * NP + j) * 2, o1 = o0 + 1;
        float2 v00 = unpack2(acc[4 * j]);
        float2 v01 = unpack2(acc[4 * j + 1]);
        float2 v10 = unpack2(acc[4 * j + 2]);
        float2 v11 = unpack2(acc[4 * j + 3]);
        int px1 = lane + 32;
        if (o0 < OCF) {
            float bb = ob[o0];
            float* p0 = om + ((b * OCF + o0) * HH + y0) * WW;
            p0[lane] = v00.x + bb;
            p0[WW + lane] = v10.x + bb;
            if (px1 < WW) { p0[px1] = v01.x + bb; p0[WW + px1] = v11.x + bb; }
        }
        if (o1 < OCF) {
            float bb = ob[o1];
            float* p1 = om + ((b * OCF + o1) * HH + y0) * WW;
            p1[lane] = v00.y + bb;
            p1[WW + lane] = v10.y + bb;
            if (px1 < WW) { p1[px1] = v01.y + bb; p1[WW + px1] = v11.y + bb; }
        }
    }
}

// ---------------------------------------------------------------------------
// Deformable conv (+ fused 1x1 residual, biases, ReLU).
// R3 block layout: one block per (b, y), 256 threads, 3 blocks/SM.
// Weights ws4[pair][t2h] float4 (2 taps) -> LDS.128 broadcast;
// cols packed colsP[t2h][px] float2 (2 taps) -> LDS.64 per pixel.
// ---------------------------------------------------------------------------
template<int K, int CB>
__global__ void __launch_bounds__(256, 3) deform_kernel(
    const float* __restrict__ x,  const float* __restrict__ w,
    const float* __restrict__ bias, const float* __restrict__ subw_g,
    const float* __restrict__ subb, float* __restrict__ out)
{
    constexpr int K2  = K * K;
    constexpr int K2h = (K2 + 1) / 2;
    constexpr int P   = K / 2;
    constexpr int NPX = K2 * 56;
    constexpr int NIT = (NPX + 255) / 256;
    constexpr int WTOT = 64 * K2h;                   // float4 entries per buffer
    constexpr int WIT  = (WTOT + 255) / 256;
    constexpr int CTOT = K2h * 64;                   // float2 entries per buffer

    const float* __restrict__ om = (K == 3) ? g_om3 : g_om5;

    extern __shared__ __align__(16) char smem_raw[];
    float4* swt   = (float4*)smem_raw;                 // [NPX]
    short4* sidx  = (short4*)(swt + NPX);              // [NPX]
    float4* ws4   = (float4*)(sidx + NPX);             // [2][64*K2h]
    float2* colsP = (float2*)(ws4 + 2 * WTOT);         // [2][K2h*64]
    float*  xrow  = (float*)(colsP + 2 * CTOT);        // [2][64]
    float2* subw2 = (float2*)(xrow + 128);             // [2][64]

    const int b    = blockIdx.x / HH;
    const int y    = blockIdx.x % HH;
    const int tid  = threadIdx.x;
    const int lane = tid & 31;
    const int g    = tid >> 5;

    // zero colsP (pad taps & pad pixels stay 0 forever)
    for (int i = tid; i < 2 * CTOT; i += 256) colsP[i] = make_float2(0.f, 0.f);

    // ---- Stage A: sampling parameters, once per block ----
    for (int i = tid; i < NPX; i += 256) {
        int tap = i / 56, pxx = i - tap * 56;
        int base = (b * 3 * K2) * HW + y * WW + pxx;
        float dy = om[base + tap * HW];
        float dx = om[base + (K2 + tap) * HW];
        float ml = om[base + (2 * K2 + tap) * HW];
        float m  = 1.f / (1.f + __expf(-ml));
        float sy = (float)(y   + tap / K - P) + dy;
        float sx = (float)(pxx + tap % K - P) + dx;
        float y0f = floorf(sy), x0f = floorf(sx);
        float ty = sy - y0f, tx = sx - x0f;
        int y0 = (int)y0f, x0 = (int)x0f, y1 = y0 + 1, x1 = x0 + 1;
        bool vy0 = (y0 >= 0) && (y0 < HH), vy1 = (y1 >= 0) && (y1 < HH);
        bool vx0 = (x0 >= 0) && (x0 < WW), vx1 = (x1 >= 0) && (x1 < WW);
        float w00 = (vy0 && vx0) ? (1.f - ty) * (1.f - tx) * m : 0.f;
        float w01 = (vy0 && vx1) ? (1.f - ty) * tx * m : 0.f;
        float w10 = (vy1 && vx0) ? ty * (1.f - tx) * m : 0.f;
        float w11 = (vy1 && vx1) ? ty * tx * m : 0.f;
        int cy0 = min(max(y0, 0), HH - 1) * WW;
        int cy1 = min(max(y1, 0), HH - 1) * WW;
        int cx0 = min(max(x0, 0), WW - 1);
        int cx1 = min(max(x1, 0), WW - 1);
        swt [i] = make_float4(w00, w01, w10, w11);
        sidx[i] = make_short4((short)(cy0 + cx0), (short)(cy0 + cx1),
                              (short)(cy1 + cx0), (short)(cy1 + cx1));
    }

    const float* xb = x + (size_t)b * CIN * HW;

    auto fill = [&](int c, int buf) {
        const float* Xc = xb + c * HW;
        float* cb = (float*)(colsP + buf * CTOT);
#pragma unroll
        for (int it = 0; it < NIT; it++) {
            int i = tid + it * 256;
            if (i < NPX) {
                short4 id = sidx[i];
                float4 wv = swt[i];
                float v = wv.x * Xc[id.x] + wv.y * Xc[id.y]
                        + wv.z * Xc[id.z] + wv.w * Xc[id.w];
                int tap = i / 56, pxx = i - tap * 56;
                cb[(tap >> 1) * 128 + pxx * 2 + (tap & 1)] = v;
            }
        }
        float4* wb = ws4 + buf * WTOT;
#pragma unroll
        for (int it = 0; it < WIT; it++) {
            int i = tid + it * 256;
            if (i < WTOT) {
                int p = i / K2h, t2h = i - p * K2h;
                int ta = 2 * t2h, tb = ta + 1;
                float4 v;
                v.x = w[(2 * p * CIN + c) * K2 + ta];
                v.y = w[((2 * p + 1) * CIN + c) * K2 + ta];
                v.z = (tb < K2) ? w[(2 * p * CIN + c) * K2 + tb] : 0.f;
                v.w = (tb < K2) ? w[((2 * p + 1) * CIN + c) * K2 + tb] : 0.f;
                wb[i] = v;
            }
        }
        if (tid < 64) {
            xrow[buf * 64 + tid] = (tid < WW) ? Xc[y * WW + tid] : 0.f;
        } else if (tid < 128) {
            int p = tid - 64;
            subw2[buf * 64 + p] = make_float2(subw_g[2 * p * CIN + c],
                                              subw_g[(2 * p + 1) * CIN + c]);
        }
    };

    __syncthreads();          // Stage A tables + cols zeros ready
    fill(0, 0);
    __syncthreads();

    u64 acc[16] = {};

    for (int c = 0; c < CIN; c++) {
        int cur = c & 1;
        if (c + 1 < CIN) fill(c + 1, cur ^ 1);

        const float2* cc = colsP + cur * CTOT;
        const ulonglong2* wrow = (const ulonglong2*)(ws4 + cur * WTOT + g * 8 * K2h);
#pragma unroll
        for (int t2h = 0; t2h < K2h; t2h++) {
            float2 cA = cc[t2h * 64 + lane];           // (tapA, tapB) @ px lane
            float2 cB = cc[t2h * 64 + lane + 32];      // px lane+32 (junk>=56 discarded; zeros)
            u64 xA0 = pack2(cA.x, cA.x), xA1 = pack2(cA.y, cA.y);
            u64 xB0 = pack2(cB.x, cB.x), xB1 = pack2(cB.y, cB.y);
#pragma unroll
            for (int j = 0; j < 8; j++) {
                ulonglong2 wv = wrow[j * K2h + t2h];   // LDS.128 broadcast
                ffma2(acc[2 * j],     xA0, wv.x);
                ffma2(acc[2 * j + 1], xB0, wv.x);
                ffma2(acc[2 * j],     xA1, wv.y);
                ffma2(acc[2 * j + 1], xB1, wv.y);
            }
        }
        // fused 1x1 residual
        {
            float s0 = xrow[cur * 64 + lane], s1 = xrow[cur * 64 + lane + 32];
            u64 xa = pack2(s0, s0), xc = pack2(s1, s1);
            const u64* srow = (const u64*)(subw2 + cur * 64 + g * 8);
#pragma unroll
            for (int j = 0; j < 8; j++) {
                u64 sv = srow[j];
                ffma2(acc[2 * j],     xa, sv);
                ffma2(acc[2 * j + 1], xc, sv);
            }
        }
        __syncthreads();
    }

#pragma unroll
    for (int j = 0; j < 8; j++) {
        int o0 = g * 16 + 2 * j, o1 = o0 + 1;
        float2 v0 = unpack2(acc[2 * j]);
        float2 v1 = unpack2(acc[2 * j + 1]);
        float bb0 = bias[o0] + subb[o0];
        float bb1 = bias[o1] + subb[o1];
        size_t base0 = ((size_t)b * (2 * OCM) + CB + o0) * HW + y * WW;
        size_t base1 = ((size_t)b * (2 * OCM) + CB + o1) * HW + y * WW;
        out[base0 + lane] = fmaxf(v0.x + bb0, 0.f);
        out[base1 + lane] = fmaxf(v0.y + bb1, 0.f);
        if (lane + 32 < WW) {
            out[base0 + lane + 32] = fmaxf(v1.x + bb0, 0.f);
            out[base1 + lane + 32] = fmaxf(v1.y + bb1, 0.f);
        }
    }
}

static constexpr int deform_smem(int K) {
    int K2 = K * K, K2h = (K2 + 1) / 2, NPX = K2 * 56;
    return NPX * 16            // swt
         + NPX * 8             // sidx
         + 2 * 64 * K2h * 16   // ws4
         + 2 * K2h * 64 * 8    // colsP
         + 128 * 4             // xrow
         + 128 * 8;            // subw2
}

// ---------------------------------------------------------------------------
// Side stream + fork/join events (created once at load; no device allocation).
// ---------------------------------------------------------------------------
struct Aux {
    cudaStream_t s1;
    cudaEvent_t  fork, join;
    Aux() {
        cudaStreamCreateWithFlags(&s1, cudaStreamNonBlocking);
        cudaEventCreateWithFlags(&fork, cudaEventDisableTiming);
        cudaEventCreateWithFlags(&join, cudaEventDisableTiming);
    }
};
static Aux g_aux;

extern "C" void kernel_launch(void* const* d_in, const int* in_sizes, int n_in,
                              void* d_out, int out_size)
{
    const float* x   = (const float*)d_in[0];
    const float* w3  = (const float*)d_in[1];
    const float* b3  = (const float*)d_in[2];
    const float* o3w = (const float*)d_in[3];
    const float* o3b = (const float*)d_in[4];
    const float* w5  = (const float*)d_in[5];
    const float* b5  = (const float*)d_in[6];
    const float* o5w = (const float*)d_in[7];
    const float* o5b = (const float*)d_in[8];
    const float* sw  = (const float*)d_in[9];
    const float* sb  = (const float*)d_in[10];
    float* out = (float*)d_out;

    constexpr int SM3 = deform_smem(3);   // ~29 KB
    constexpr int SM5 = deform_smem(5);   // ~73.3 KB
    cudaFuncSetAttribute((const void*)deform_kernel<3, 0>,
                         cudaFuncAttributeMaxDynamicSharedMemorySize, SM3);
    cudaFuncSetAttribute((const void*)deform_kernel<5, OCM>,
                         cudaFuncAttributeMaxDynamicSharedMemorySize, SM5);

    dim3 gridO(BN * (HH / 2));
    dim3 gridD(BN * HH);

    cudaEventRecord(g_aux.fork, 0);
    cudaStreamWaitEvent(g_aux.s1, g_aux.fork, 0);

    offset_conv_kernel<3><<<gridO, 256, 0, g_aux.s1>>>(x, o3w, o3b);
    deform_kernel<3, 0  ><<<gridD, 256, SM3, g_aux.s1>>>(x, w3, b3, sw, sb, out);

    offset_conv_kernel<5><<<gridO, 256>>>(x, o5w, o5b);
    deform_kernel<5, OCM><<<gridD, 256, SM5>>>(x, w5, b5, sw, sb, out);

    cudaEventRecord(g_aux.join, g_aux.s1);
    cudaStreamWaitEvent(0, g_aux.join, 0);
}